// round 12
// baseline (speedup 1.0000x reference)
#include <cuda_runtime.h>
#include <cuda_fp16.h>
#include <cstdint>

#define NN 100000
#define NE 1600000
#define FH 128
#define FO 64
#define NBLK 391             // ceil(NN/256)

__device__ int      g_dege[NN];      // real in-degree (no self loop)
__device__ float    g_dinv[NN];
__device__ int      g_off[NN + 1];
__device__ int      g_cur[NN];
__device__ int2     g_edge[NE];      // {src, bitcast(dinv[src])} per CSR slot
__device__ unsigned long long g_stat[NBLK];  // decoupled-lookback state
__device__ __half   g_h1[(size_t)NN * FH];   // fp16, unscaled
__device__ __half   g_agg[(size_t)NN * FH];  // fp16 (GEMM2 input, post relu+dropout)
__device__ __half   g_h2[(size_t)NN * FO];   // fp16, pre-scaled by dinv[row]

// ---------------- zero (degrees + scan state) ----------------
__global__ void k_zero() {
    int i = blockIdx.x * blockDim.x + threadIdx.x;   // 25088 threads
    if (i < NN / 4) *(int4*)(g_dege + i * 4) = make_int4(0, 0, 0, 0);
    if (i < NBLK) g_stat[i] = 0ULL;
}

// ---------------- degree count: 4 edges per thread, RED (no return) ----------------
__device__ __forceinline__ void red_add1(int* p) {
    asm volatile("red.global.add.s32 [%0], 1;" :: "l"(p) : "memory");
}
__global__ void __launch_bounds__(512) k_deg_count(const int* __restrict__ dst) {
    int t = blockIdx.x * blockDim.x + threadIdx.x;   // NE/4 threads
    if (t >= NE / 4) return;
    int4 d = __ldg((const int4*)dst + t);
    red_add1(&g_dege[d.x]);
    red_add1(&g_dege[d.y]);
    red_add1(&g_dege[d.z]);
    red_add1(&g_dege[d.w]);
}

// ---------------- CSR offsets: single-kernel decoupled-lookback scan ----------------
__global__ void __launch_bounds__(256) k_csr_scan() {
    __shared__ int sh[256];
    __shared__ int exc_sh;
    const int b = blockIdx.x, t = threadIdx.x;
    const int i = b * 256 + t;
    int d = (i < NN) ? g_dege[i] : 0;

    sh[t] = d;
    __syncthreads();
#pragma unroll
    for (int o = 1; o < 256; o <<= 1) {
        int v = (t >= o) ? sh[t - o] : 0;
        __syncthreads();
        sh[t] += v;
        __syncthreads();
    }
    const unsigned blocksum = (unsigned)sh[255];

    if (b == 0) {
        if (t == 0) {
            atomicExch(&g_stat[0], (2ULL << 32) | blocksum);
            exc_sh = 0;
        }
    } else if (t < 32) {
        if (t == 0) atomicExch(&g_stat[b], (1ULL << 32) | blocksum);
        __syncwarp();
        unsigned running = 0;
        int base = b - 1;
        while (true) {
            int p = base - t;
            unsigned long long s;
            if (p >= 0) {
                const volatile unsigned long long* ps =
                    (const volatile unsigned long long*)(g_stat + p);
                do { s = *ps; } while ((unsigned)(s >> 32) == 0u);
            } else {
                s = (2ULL << 32);
            }
            unsigned ballot = __ballot_sync(0xffffffffu, (unsigned)(s >> 32) == 2u);
            unsigned val = (unsigned)s;
            unsigned contrib;
            bool done = (ballot != 0);
            if (done) {
                int firstp = __ffs(ballot) - 1;
                contrib = (t <= firstp) ? val : 0u;
            } else {
                contrib = val;
            }
#pragma unroll
            for (int o = 16; o > 0; o >>= 1)
                contrib += __shfl_down_sync(0xffffffffu, contrib, o);
            if (t == 0) running += contrib;
            if (done) break;
            base -= 32;
        }
        if (t == 0) {
            atomicExch(&g_stat[b], (2ULL << 32) | (blocksum + running));
            exc_sh = (int)running;
        }
    }
    __syncthreads();

    if (i < NN) {
        int off = exc_sh + sh[t] - d;   // exclusive
        g_off[i] = off;
        g_cur[i] = off;
        g_dinv[i] = rsqrtf((float)(d + 1));   // +1 self loop
        if (i == NN - 1) g_off[NN] = off + d;
    }
}

// ---------------- fill: 4 edges per thread ----------------
__global__ void __launch_bounds__(512) k_fill(const int* __restrict__ src,
                                              const int* __restrict__ dst) {
    int t = blockIdx.x * blockDim.x + threadIdx.x;   // NE/4 threads
    if (t >= NE / 4) return;
    int4 s4 = __ldg((const int4*)src + t);
    int4 d4 = __ldg((const int4*)dst + t);
#pragma unroll
    for (int j = 0; j < 4; j++) {
        int s = (j == 0) ? s4.x : (j == 1) ? s4.y : (j == 2) ? s4.z : s4.w;
        int d = (j == 0) ? d4.x : (j == 1) ? d4.y : (j == 2) ? d4.z : d4.w;
        int slot = atomicAdd(&g_cur[d], 1);
        g_edge[slot] = make_int2(s, __float_as_int(__ldg(g_dinv + s)));
    }
}

// ---------------- JAX threefry2x32 (partitionable path) ----------------
__device__ __forceinline__ uint2 threefry2x32_0_42(unsigned x0, unsigned x1) {
    const unsigned ks0 = 0u, ks1 = 42u, ks2 = 0u ^ 42u ^ 0x1BD11BDAu;
    x0 += ks0; x1 += ks1;
#define TF_R(r) { x0 += x1; x1 = __funnelshift_l(x1, x1, (r)); x1 ^= x0; }
    TF_R(13) TF_R(15) TF_R(26) TF_R(6)
    x0 += ks1; x1 += ks2 + 1u;
    TF_R(17) TF_R(29) TF_R(16) TF_R(24)
    x0 += ks2; x1 += ks0 + 2u;
    TF_R(13) TF_R(15) TF_R(26) TF_R(6)
    x0 += ks0; x1 += ks1 + 3u;
    TF_R(17) TF_R(29) TF_R(16) TF_R(24)
    x0 += ks1; x1 += ks2 + 4u;
    TF_R(13) TF_R(15) TF_R(26) TF_R(6)
    x0 += ks2; x1 += ks0 + 5u;
#undef TF_R
    return make_uint2(x0, x1);
}
__device__ __forceinline__ float drop_mul(unsigned i) {
    uint2 o = threefry2x32_0_42(0u, i);
    return ((int)(o.x ^ o.y) >= 0) ? 2.f : 0.f;
}

// ---------------- fp16 tensor-core GEMM: C[NN x BN] = A[NN x 128] * W[128 x BN] ----------------
__device__ __forceinline__ void mma_f16(float* c, const uint32_t* a, uint32_t b0, uint32_t b1) {
    asm volatile(
        "mma.sync.aligned.m16n8k16.row.col.f32.f16.f16.f32 "
        "{%0,%1,%2,%3}, {%4,%5,%6,%7}, {%8,%9}, {%0,%1,%2,%3};\n"
        : "+f"(c[0]), "+f"(c[1]), "+f"(c[2]), "+f"(c[3])
        : "r"(a[0]), "r"(a[1]), "r"(a[2]), "r"(a[3]), "r"(b0), "r"(b1));
}

template <int BN, bool A_HALF, bool SCALE>
__device__ __forceinline__ void gemm_f16_body(const void* __restrict__ Aptr,
                                              const float* __restrict__ W,
                                              __half* __restrict__ C) {
    __shared__ uint32_t As[128][36];
    __shared__ uint32_t Wt[BN][36];
    const int tid = threadIdx.x;
    const int lane = tid & 31, wid = tid >> 5;
    const int warp_m = wid & 3, warp_n = wid >> 2;
    const int row0 = blockIdx.x * 128;
    constexpr int WN = BN / 2;
    constexpr int TN = WN / 8;

    float c[2][TN][4];
#pragma unroll
    for (int i = 0; i < 2; i++)
#pragma unroll
        for (int j = 0; j < TN; j++)
#pragma unroll
            for (int q = 0; q < 4; q++) c[i][j][q] = 0.f;

    for (int k0 = 0; k0 < 128; k0 += 64) {
        if (A_HALF) {
            const uint4* Ab = (const uint4*)Aptr;
#pragma unroll
            for (int it = 0; it < 4; it++) {
                int idx = tid + it * 256;
                int r = idx >> 3, u = idx & 7;
                int gr = row0 + r; if (gr >= NN) gr = 0;
                uint4 v = __ldg(Ab + (size_t)gr * 16 + (k0 >> 3) + u);
                *(uint4*)&As[r][u * 4] = v;
            }
        } else {
            const float4* Af = (const float4*)Aptr;
#pragma unroll
            for (int it = 0; it < 8; it++) {
                int idx = tid + it * 256;
                int r = idx >> 4, u = idx & 15;
                int gr = row0 + r; if (gr >= NN) gr = 0;
                float4 v = __ldg(Af + (size_t)gr * 32 + (k0 >> 2) + u);
                half2 h0 = __floats2half2_rn(v.x, v.y);
                half2 h1 = __floats2half2_rn(v.z, v.w);
                As[r][u * 2 + 0] = *(uint32_t*)&h0;
                As[r][u * 2 + 1] = *(uint32_t*)&h1;
            }
        }
        constexpr int WIT = (32 * BN) / 256;
#pragma unroll
        for (int it = 0; it < WIT; it++) {
            int idx = tid + it * 256;
            int n = idx % BN, k2 = idx / BN;
            half2 h = __floats2half2_rn(__ldg(W + (size_t)(k0 + 2 * k2) * BN + n),
                                        __ldg(W + (size_t)(k0 + 2 * k2 + 1) * BN + n));
            Wt[n][k2] = *(uint32_t*)&h;
        }
        __syncthreads();

#pragma unroll
        for (int kk = 0; kk < 4; kk++) {
            const int K2 = kk * 8;
            const int ar = warp_m * 32 + (lane >> 2);
            uint32_t a[2][4];
#pragma unroll
            for (int tm = 0; tm < 2; tm++) {
                a[tm][0] = As[ar + tm * 16][K2 + (lane & 3)];
                a[tm][1] = As[ar + tm * 16 + 8][K2 + (lane & 3)];
                a[tm][2] = As[ar + tm * 16][K2 + 4 + (lane & 3)];
                a[tm][3] = As[ar + tm * 16 + 8][K2 + 4 + (lane & 3)];
            }
#pragma unroll
            for (int tn = 0; tn < TN; tn++) {
                int bn = warp_n * WN + tn * 8 + (lane >> 2);
                uint32_t b0 = Wt[bn][K2 + (lane & 3)];
                uint32_t b1 = Wt[bn][K2 + 4 + (lane & 3)];
                mma_f16(c[0][tn], a[0], b0, b1);
                mma_f16(c[1][tn], a[1], b0, b1);
            }
        }
        __syncthreads();
    }

#pragma unroll
    for (int tm = 0; tm < 2; tm++) {
        int rbase = row0 + warp_m * 32 + tm * 16 + (lane >> 2);
#pragma unroll
        for (int half = 0; half < 2; half++) {
            int rr = rbase + half * 8;
            if (rr < NN) {
                float sc = SCALE ? __ldg(g_dinv + rr) : 1.f;
#pragma unroll
                for (int tn = 0; tn < TN; tn++) {
                    int n = warp_n * WN + tn * 8 + 2 * (lane & 3);
                    *(half2*)(C + (size_t)rr * BN + n) =
                        __floats2half2_rn(c[tm][tn][2 * half] * sc,
                                          c[tm][tn][2 * half + 1] * sc);
                }
            }
        }
    }
}

__global__ void __launch_bounds__(256) k_gemm1(const float* __restrict__ A,
                                               const float* __restrict__ W) {
    gemm_f16_body<128, false, false>(A, W, g_h1);
}
__global__ void __launch_bounds__(256) k_gemm2(const float* __restrict__ W) {
    gemm_f16_body<64, true, true>(g_agg, W, g_h2);
}

// ---------------- layer-1 aggregation: 2 warps per node (64 feat each), fused relu+dropout ----------------
__device__ __forceinline__ void acc_h2(float2& ae, uint32_t u, float w) {
    float2 f = __half22float2(*reinterpret_cast<half2*>(&u));
    ae.x = fmaf(f.x, w, ae.x);
    ae.y = fmaf(f.y, w, ae.y);
}

__global__ void __launch_bounds__(256) k_agg1(const float* __restrict__ b1) {
    int w = (blockIdx.x * 256 + threadIdx.x) >> 5;   // global warp id, 2 per node
    int d = w >> 1;
    if (d >= NN) return;
    int lane = threadIdx.x & 31;
    int col = (w & 1) * 32 + lane;                   // half2 column 0..63
    float dind = __ldg(g_dinv + d);

    const uint32_t* hb = (const uint32_t*)g_h1;      // 64 half2 per row
    float2 ae = make_float2(0.f, 0.f);
    acc_h2(ae, __ldg(hb + (size_t)d * 64 + col), dind);   // self term

    int beg = __ldg(g_off + d), end = __ldg(g_off + d + 1);
    int i = beg;
    for (; i + 4 <= end; i += 4) {
        int2 e0 = __ldg(g_edge + i + 0);
        int2 e1 = __ldg(g_edge + i + 1);
        int2 e2 = __ldg(g_edge + i + 2);
        int2 e3 = __ldg(g_edge + i + 3);
        uint32_t u0 = __ldg(hb + (size_t)e0.x * 64 + col);
        uint32_t u1 = __ldg(hb + (size_t)e1.x * 64 + col);
        uint32_t u2 = __ldg(hb + (size_t)e2.x * 64 + col);
        uint32_t u3 = __ldg(hb + (size_t)e3.x * 64 + col);
        acc_h2(ae, u0, __int_as_float(e0.y));
        acc_h2(ae, u1, __int_as_float(e1.y));
        acc_h2(ae, u2, __int_as_float(e2.y));
        acc_h2(ae, u3, __int_as_float(e3.y));
    }
    for (; i < end; i++) {
        int2 e = __ldg(g_edge + i);
        acc_h2(ae, __ldg(hb + (size_t)e.x * 64 + col), __int_as_float(e.y));
    }

    int f = col * 2;                                 // feature index of .x
    float2 bv = __ldg((const float2*)(b1 + f));
    unsigned base = (unsigned)d * 128u + (unsigned)f;
    float m0 = drop_mul(base + 0), m1 = drop_mul(base + 1);
    float ax = fmaxf(fmaf(ae.x, dind, bv.x), 0.f) * m0;
    float ay = fmaxf(fmaf(ae.y, dind, bv.y), 0.f) * m1;

    half2 h = __floats2half2_rn(ax, ay);
    ((uint32_t*)g_agg)[(size_t)d * 64 + col] = *(uint32_t*)&h;
}

// ---------------- layer-2 aggregation: warp per node (2 feat per lane), h2 pre-scaled ----------------
__global__ void __launch_bounds__(256) k_agg2(const float* __restrict__ b2,
                                              float* __restrict__ out) {
    int d = (blockIdx.x * 256 + threadIdx.x) >> 5;
    if (d >= NN) return;
    int lane = threadIdx.x & 31;                     // half2 column 0..31
    float dind = __ldg(g_dinv + d);

    const uint32_t* hb = (const uint32_t*)g_h2;      // 32 half2 per row
    float2 ae = make_float2(0.f, 0.f);
    acc_h2(ae, __ldg(hb + (size_t)d * 32 + lane), 1.f);   // self term (pre-scaled)

    int beg = __ldg(g_off + d), end = __ldg(g_off + d + 1);
    int i = beg;
    for (; i + 4 <= end; i += 4) {
        int2 e0 = __ldg(g_edge + i + 0);
        int2 e1 = __ldg(g_edge + i + 1);
        int2 e2 = __ldg(g_edge + i + 2);
        int2 e3 = __ldg(g_edge + i + 3);
        uint32_t u0 = __ldg(hb + (size_t)e0.x * 32 + lane);
        uint32_t u1 = __ldg(hb + (size_t)e1.x * 32 + lane);
        uint32_t u2 = __ldg(hb + (size_t)e2.x * 32 + lane);
        uint32_t u3 = __ldg(hb + (size_t)e3.x * 32 + lane);
        acc_h2(ae, u0, 1.f); acc_h2(ae, u1, 1.f);
        acc_h2(ae, u2, 1.f); acc_h2(ae, u3, 1.f);
    }
    for (; i < end; i++) {
        int2 e = __ldg(g_edge + i);
        acc_h2(ae, __ldg(hb + (size_t)e.x * 32 + lane), 1.f);
    }

    int f = lane * 2;
    float2 bv = __ldg((const float2*)(b2 + f));
    float2 acc;
    acc.x = fmaf(ae.x, dind, bv.x);
    acc.y = fmaf(ae.y, dind, bv.y);
    *(float2*)(out + (size_t)d * 64 + f) = acc;
}

// ---------------- launch: gemm1 forked, CSR on default ----------------
extern "C" void kernel_launch(void* const* d_in, const int* in_sizes, int n_in,
                              void* d_out, int out_size) {
    const float* x  = (const float*)d_in[0];
    const int*   ei = (const int*)d_in[1];
    const float* W1 = (const float*)d_in[2];
    const float* b1 = (const float*)d_in[3];
    const float* W2 = (const float*)d_in[4];
    const float* b2 = (const float*)d_in[5];
    const int* src = ei;
    const int* dst = ei + NE;
    float* out = (float*)d_out;

    static cudaStream_t sB = nullptr;
    static cudaEvent_t evRoot = nullptr, evB = nullptr;
    if (sB == nullptr) {
        cudaStreamCreateWithFlags(&sB, cudaStreamNonBlocking);
        cudaEventCreateWithFlags(&evRoot, cudaEventDisableTiming);
        cudaEventCreateWithFlags(&evB, cudaEventDisableTiming);
    }

    cudaEventRecord(evRoot, 0);
    cudaStreamWaitEvent(sB, evRoot, 0);

    // stream B: GEMM1 (fp16 tensor cores) — hidden under CSR build
    k_gemm1<<<(NN + 127) / 128, 256, 0, sB>>>(x, W1);
    cudaEventRecord(evB, sB);

    // default stream: CSR build
    k_zero<<<98, 256>>>();
    k_deg_count<<<(NE / 4 + 511) / 512, 512>>>(dst);
    k_csr_scan<<<NBLK, 256>>>();
    k_fill<<<(NE / 4 + 511) / 512, 512>>>(src, dst);

    cudaStreamWaitEvent(0, evB, 0);

    k_agg1<<<(NN * 64 + 255) / 256, 256>>>(b1);       // 2 warps/node, fused relu+dropout
    k_gemm2<<<(NN + 127) / 128, 256>>>(W2);
    k_agg2<<<(NN * 32 + 255) / 256, 256>>>(b2, out);  // 1 warp/node
}

// round 13
// speedup vs baseline: 1.1046x; 1.1046x over previous
#include <cuda_runtime.h>
#include <cuda_fp16.h>
#include <cstdint>

#define NN 100000
#define NE 1600000
#define FH 128
#define FO 64
#define NBLK 391             // ceil(NN/256)

__device__ int      g_dege[NN];      // real in-degree (no self loop)
__device__ float    g_dinv[NN];
__device__ int      g_off[NN + 1];
__device__ int      g_cur[NN];
__device__ int2     g_edge[NE];      // {src, bitcast(dinv[src])} per CSR slot
__device__ unsigned long long g_stat[NBLK];  // decoupled-lookback state
__device__ __half   g_h1[(size_t)NN * FH];   // fp16, unscaled
__device__ __half   g_agg[(size_t)NN * FH];  // fp16 (GEMM2 input, post relu+dropout)
__device__ __half   g_h2[(size_t)NN * FO];   // fp16, pre-scaled by dinv[row]

// ---------------- zero (degrees + scan state) ----------------
__global__ void k_zero() {
    int i = blockIdx.x * blockDim.x + threadIdx.x;   // 25088 threads
    if (i < NN / 4) *(int4*)(g_dege + i * 4) = make_int4(0, 0, 0, 0);
    if (i < NBLK) g_stat[i] = 0ULL;
}

// ---------------- degree count: 4 edges per thread, RED (no return) ----------------
__device__ __forceinline__ void red_add1(int* p) {
    asm volatile("red.global.add.s32 [%0], 1;" :: "l"(p) : "memory");
}
__global__ void __launch_bounds__(512) k_deg_count(const int* __restrict__ dst) {
    int t = blockIdx.x * blockDim.x + threadIdx.x;   // NE/4 threads
    if (t >= NE / 4) return;
    int4 d = __ldg((const int4*)dst + t);
    red_add1(&g_dege[d.x]);
    red_add1(&g_dege[d.y]);
    red_add1(&g_dege[d.z]);
    red_add1(&g_dege[d.w]);
}

// ---------------- CSR offsets: single-kernel decoupled-lookback scan ----------------
__global__ void __launch_bounds__(256) k_csr_scan() {
    __shared__ int sh[256];
    __shared__ int exc_sh;
    const int b = blockIdx.x, t = threadIdx.x;
    const int i = b * 256 + t;
    int d = (i < NN) ? g_dege[i] : 0;

    sh[t] = d;
    __syncthreads();
#pragma unroll
    for (int o = 1; o < 256; o <<= 1) {
        int v = (t >= o) ? sh[t - o] : 0;
        __syncthreads();
        sh[t] += v;
        __syncthreads();
    }
    const unsigned blocksum = (unsigned)sh[255];

    if (b == 0) {
        if (t == 0) {
            atomicExch(&g_stat[0], (2ULL << 32) | blocksum);
            exc_sh = 0;
        }
    } else if (t < 32) {
        if (t == 0) atomicExch(&g_stat[b], (1ULL << 32) | blocksum);
        __syncwarp();
        unsigned running = 0;
        int base = b - 1;
        while (true) {
            int p = base - t;
            unsigned long long s;
            if (p >= 0) {
                const volatile unsigned long long* ps =
                    (const volatile unsigned long long*)(g_stat + p);
                do { s = *ps; } while ((unsigned)(s >> 32) == 0u);
            } else {
                s = (2ULL << 32);
            }
            unsigned ballot = __ballot_sync(0xffffffffu, (unsigned)(s >> 32) == 2u);
            unsigned val = (unsigned)s;
            unsigned contrib;
            bool done = (ballot != 0);
            if (done) {
                int firstp = __ffs(ballot) - 1;
                contrib = (t <= firstp) ? val : 0u;
            } else {
                contrib = val;
            }
#pragma unroll
            for (int o = 16; o > 0; o >>= 1)
                contrib += __shfl_down_sync(0xffffffffu, contrib, o);
            if (t == 0) running += contrib;
            if (done) break;
            base -= 32;
        }
        if (t == 0) {
            atomicExch(&g_stat[b], (2ULL << 32) | (blocksum + running));
            exc_sh = (int)running;
        }
    }
    __syncthreads();

    if (i < NN) {
        int off = exc_sh + sh[t] - d;   // exclusive
        g_off[i] = off;
        g_cur[i] = off;
        g_dinv[i] = rsqrtf((float)(d + 1));   // +1 self loop
        if (i == NN - 1) g_off[NN] = off + d;
    }
}

// ---------------- fill: 4 edges per thread ----------------
__global__ void __launch_bounds__(512) k_fill(const int* __restrict__ src,
                                              const int* __restrict__ dst) {
    int t = blockIdx.x * blockDim.x + threadIdx.x;   // NE/4 threads
    if (t >= NE / 4) return;
    int4 s4 = __ldg((const int4*)src + t);
    int4 d4 = __ldg((const int4*)dst + t);
#pragma unroll
    for (int j = 0; j < 4; j++) {
        int s = (j == 0) ? s4.x : (j == 1) ? s4.y : (j == 2) ? s4.z : s4.w;
        int d = (j == 0) ? d4.x : (j == 1) ? d4.y : (j == 2) ? d4.z : d4.w;
        int slot = atomicAdd(&g_cur[d], 1);
        g_edge[slot] = make_int2(s, __float_as_int(__ldg(g_dinv + s)));
    }
}

// ---------------- JAX threefry2x32 (partitionable path) ----------------
__device__ __forceinline__ uint2 threefry2x32_0_42(unsigned x0, unsigned x1) {
    const unsigned ks0 = 0u, ks1 = 42u, ks2 = 0u ^ 42u ^ 0x1BD11BDAu;
    x0 += ks0; x1 += ks1;
#define TF_R(r) { x0 += x1; x1 = __funnelshift_l(x1, x1, (r)); x1 ^= x0; }
    TF_R(13) TF_R(15) TF_R(26) TF_R(6)
    x0 += ks1; x1 += ks2 + 1u;
    TF_R(17) TF_R(29) TF_R(16) TF_R(24)
    x0 += ks2; x1 += ks0 + 2u;
    TF_R(13) TF_R(15) TF_R(26) TF_R(6)
    x0 += ks0; x1 += ks1 + 3u;
    TF_R(17) TF_R(29) TF_R(16) TF_R(24)
    x0 += ks1; x1 += ks2 + 4u;
    TF_R(13) TF_R(15) TF_R(26) TF_R(6)
    x0 += ks2; x1 += ks0 + 5u;
#undef TF_R
    return make_uint2(x0, x1);
}
__device__ __forceinline__ float drop_mul(unsigned i) {
    uint2 o = threefry2x32_0_42(0u, i);
    return ((int)(o.x ^ o.y) >= 0) ? 2.f : 0.f;
}

// ---------------- fp16 tensor-core GEMM: C[NN x BN] = A[NN x 128] * W[128 x BN] ----------------
__device__ __forceinline__ void mma_f16(float* c, const uint32_t* a, uint32_t b0, uint32_t b1) {
    asm volatile(
        "mma.sync.aligned.m16n8k16.row.col.f32.f16.f16.f32 "
        "{%0,%1,%2,%3}, {%4,%5,%6,%7}, {%8,%9}, {%0,%1,%2,%3};\n"
        : "+f"(c[0]), "+f"(c[1]), "+f"(c[2]), "+f"(c[3])
        : "r"(a[0]), "r"(a[1]), "r"(a[2]), "r"(a[3]), "r"(b0), "r"(b1));
}

template <int BN, bool A_HALF, bool SCALE>
__device__ __forceinline__ void gemm_f16_body(const void* __restrict__ Aptr,
                                              const float* __restrict__ W,
                                              __half* __restrict__ C) {
    __shared__ uint32_t As[128][36];
    __shared__ uint32_t Wt[BN][36];
    const int tid = threadIdx.x;
    const int lane = tid & 31, wid = tid >> 5;
    const int warp_m = wid & 3, warp_n = wid >> 2;
    const int row0 = blockIdx.x * 128;
    constexpr int WN = BN / 2;
    constexpr int TN = WN / 8;

    float c[2][TN][4];
#pragma unroll
    for (int i = 0; i < 2; i++)
#pragma unroll
        for (int j = 0; j < TN; j++)
#pragma unroll
            for (int q = 0; q < 4; q++) c[i][j][q] = 0.f;

    for (int k0 = 0; k0 < 128; k0 += 64) {
        if (A_HALF) {
            const uint4* Ab = (const uint4*)Aptr;
#pragma unroll
            for (int it = 0; it < 4; it++) {
                int idx = tid + it * 256;
                int r = idx >> 3, u = idx & 7;
                int gr = row0 + r; if (gr >= NN) gr = 0;
                uint4 v = __ldg(Ab + (size_t)gr * 16 + (k0 >> 3) + u);
                *(uint4*)&As[r][u * 4] = v;
            }
        } else {
            const float4* Af = (const float4*)Aptr;
#pragma unroll
            for (int it = 0; it < 8; it++) {
                int idx = tid + it * 256;
                int r = idx >> 4, u = idx & 15;
                int gr = row0 + r; if (gr >= NN) gr = 0;
                float4 v = __ldg(Af + (size_t)gr * 32 + (k0 >> 2) + u);
                half2 h0 = __floats2half2_rn(v.x, v.y);
                half2 h1 = __floats2half2_rn(v.z, v.w);
                As[r][u * 2 + 0] = *(uint32_t*)&h0;
                As[r][u * 2 + 1] = *(uint32_t*)&h1;
            }
        }
        constexpr int WIT = (32 * BN) / 256;
#pragma unroll
        for (int it = 0; it < WIT; it++) {
            int idx = tid + it * 256;
            int n = idx % BN, k2 = idx / BN;
            half2 h = __floats2half2_rn(__ldg(W + (size_t)(k0 + 2 * k2) * BN + n),
                                        __ldg(W + (size_t)(k0 + 2 * k2 + 1) * BN + n));
            Wt[n][k2] = *(uint32_t*)&h;
        }
        __syncthreads();

#pragma unroll
        for (int kk = 0; kk < 4; kk++) {
            const int K2 = kk * 8;
            const int ar = warp_m * 32 + (lane >> 2);
            uint32_t a[2][4];
#pragma unroll
            for (int tm = 0; tm < 2; tm++) {
                a[tm][0] = As[ar + tm * 16][K2 + (lane & 3)];
                a[tm][1] = As[ar + tm * 16 + 8][K2 + (lane & 3)];
                a[tm][2] = As[ar + tm * 16][K2 + 4 + (lane & 3)];
                a[tm][3] = As[ar + tm * 16 + 8][K2 + 4 + (lane & 3)];
            }
#pragma unroll
            for (int tn = 0; tn < TN; tn++) {
                int bn = warp_n * WN + tn * 8 + (lane >> 2);
                uint32_t b0 = Wt[bn][K2 + (lane & 3)];
                uint32_t b1 = Wt[bn][K2 + 4 + (lane & 3)];
                mma_f16(c[0][tn], a[0], b0, b1);
                mma_f16(c[1][tn], a[1], b0, b1);
            }
        }
        __syncthreads();
    }

#pragma unroll
    for (int tm = 0; tm < 2; tm++) {
        int rbase = row0 + warp_m * 32 + tm * 16 + (lane >> 2);
#pragma unroll
        for (int half = 0; half < 2; half++) {
            int rr = rbase + half * 8;
            if (rr < NN) {
                float sc = SCALE ? __ldg(g_dinv + rr) : 1.f;
#pragma unroll
                for (int tn = 0; tn < TN; tn++) {
                    int n = warp_n * WN + tn * 8 + 2 * (lane & 3);
                    *(half2*)(C + (size_t)rr * BN + n) =
                        __floats2half2_rn(c[tm][tn][2 * half] * sc,
                                          c[tm][tn][2 * half + 1] * sc);
                }
            }
        }
    }
}

__global__ void __launch_bounds__(256) k_gemm1(const float* __restrict__ A,
                                               const float* __restrict__ W) {
    gemm_f16_body<128, false, false>(A, W, g_h1);
}
__global__ void __launch_bounds__(256) k_gemm2(const float* __restrict__ W) {
    gemm_f16_body<64, true, true>(g_agg, W, g_h2);
}

// ---------------- layer-1 aggregation: warp per node, unroll-8 gather, fused relu+dropout ----------------
__device__ __forceinline__ void acc_h4(float4& ae, uint2 u, float w) {
    float2 f0 = __half22float2(*reinterpret_cast<half2*>(&u.x));
    float2 f1 = __half22float2(*reinterpret_cast<half2*>(&u.y));
    ae.x = fmaf(f0.x, w, ae.x); ae.y = fmaf(f0.y, w, ae.y);
    ae.z = fmaf(f1.x, w, ae.z); ae.w = fmaf(f1.y, w, ae.w);
}

__global__ void __launch_bounds__(256) k_agg1(const float* __restrict__ b1) {
    int d = (blockIdx.x * 256 + threadIdx.x) >> 5;
    if (d >= NN) return;
    int lane = threadIdx.x & 31;
    float dind = __ldg(g_dinv + d);

    const uint2* hb = (const uint2*)g_h1;
    float4 ae = make_float4(0.f, 0.f, 0.f, 0.f);
    acc_h4(ae, __ldg(hb + (size_t)d * 32 + lane), dind);   // self term

    int beg = __ldg(g_off + d), end = __ldg(g_off + d + 1);
    int i = beg;
    for (; i + 8 <= end; i += 8) {
        int2 e[8];
        uint2 u[8];
#pragma unroll
        for (int j = 0; j < 8; j++) e[j] = __ldg(g_edge + i + j);
#pragma unroll
        for (int j = 0; j < 8; j++) u[j] = __ldg(hb + (size_t)e[j].x * 32 + lane);
#pragma unroll
        for (int j = 0; j < 8; j++) acc_h4(ae, u[j], __int_as_float(e[j].y));
    }
    for (; i + 4 <= end; i += 4) {
        int2 e0 = __ldg(g_edge + i + 0);
        int2 e1 = __ldg(g_edge + i + 1);
        int2 e2 = __ldg(g_edge + i + 2);
        int2 e3 = __ldg(g_edge + i + 3);
        uint2 u0 = __ldg(hb + (size_t)e0.x * 32 + lane);
        uint2 u1 = __ldg(hb + (size_t)e1.x * 32 + lane);
        uint2 u2 = __ldg(hb + (size_t)e2.x * 32 + lane);
        uint2 u3 = __ldg(hb + (size_t)e3.x * 32 + lane);
        acc_h4(ae, u0, __int_as_float(e0.y));
        acc_h4(ae, u1, __int_as_float(e1.y));
        acc_h4(ae, u2, __int_as_float(e2.y));
        acc_h4(ae, u3, __int_as_float(e3.y));
    }
    for (; i < end; i++) {
        int2 e = __ldg(g_edge + i);
        acc_h4(ae, __ldg(hb + (size_t)e.x * 32 + lane), __int_as_float(e.y));
    }

    int f = lane * 4;
    float4 bv = __ldg((const float4*)(b1 + f));
    unsigned base = (unsigned)d * 128u + (unsigned)f;
    float m0 = drop_mul(base + 0), m1 = drop_mul(base + 1);
    float m2 = drop_mul(base + 2), m3 = drop_mul(base + 3);
    float4 acc;
    acc.x = fmaxf(fmaf(ae.x, dind, bv.x), 0.f) * m0;
    acc.y = fmaxf(fmaf(ae.y, dind, bv.y), 0.f) * m1;
    acc.z = fmaxf(fmaf(ae.z, dind, bv.z), 0.f) * m2;
    acc.w = fmaxf(fmaf(ae.w, dind, bv.w), 0.f) * m3;

    half2 h0 = __floats2half2_rn(acc.x, acc.y);
    half2 h1 = __floats2half2_rn(acc.z, acc.w);
    uint2 st = make_uint2(*(uint32_t*)&h0, *(uint32_t*)&h1);
    *(uint2*)(g_agg + (size_t)d * 128 + f) = st;
}

// ---------------- layer-2 aggregation: half warp per node, unroll-8, h2 pre-scaled ----------------
__global__ void __launch_bounds__(256) k_agg2(const float* __restrict__ b2,
                                              float* __restrict__ out) {
    int t = blockIdx.x * 256 + threadIdx.x;
    int d = t >> 4;
    if (d >= NN) return;
    int l = t & 15;
    float dind = __ldg(g_dinv + d);

    const uint2* hb = (const uint2*)g_h2;
    float4 ae = make_float4(0.f, 0.f, 0.f, 0.f);
    acc_h4(ae, __ldg(hb + (size_t)d * 16 + l), 1.f);   // self term (pre-scaled)

    int beg = __ldg(g_off + d), end = __ldg(g_off + d + 1);
    int i = beg;
    for (; i + 8 <= end; i += 8) {
        int2 e[8];
        uint2 u[8];
#pragma unroll
        for (int j = 0; j < 8; j++) e[j] = __ldg(g_edge + i + j);
#pragma unroll
        for (int j = 0; j < 8; j++) u[j] = __ldg(hb + (size_t)e[j].x * 16 + l);
#pragma unroll
        for (int j = 0; j < 8; j++) acc_h4(ae, u[j], 1.f);
    }
    for (; i + 4 <= end; i += 4) {
        int2 e0 = __ldg(g_edge + i + 0);
        int2 e1 = __ldg(g_edge + i + 1);
        int2 e2 = __ldg(g_edge + i + 2);
        int2 e3 = __ldg(g_edge + i + 3);
        uint2 u0 = __ldg(hb + (size_t)e0.x * 16 + l);
        uint2 u1 = __ldg(hb + (size_t)e1.x * 16 + l);
        uint2 u2 = __ldg(hb + (size_t)e2.x * 16 + l);
        uint2 u3 = __ldg(hb + (size_t)e3.x * 16 + l);
        acc_h4(ae, u0, 1.f); acc_h4(ae, u1, 1.f);
        acc_h4(ae, u2, 1.f); acc_h4(ae, u3, 1.f);
    }
    for (; i < end; i++) {
        int2 e = __ldg(g_edge + i);
        acc_h4(ae, __ldg(hb + (size_t)e.x * 16 + l), 1.f);
    }

    float4 bv = __ldg((const float4*)(b2 + l * 4));
    float4 acc;
    acc.x = fmaf(ae.x, dind, bv.x);
    acc.y = fmaf(ae.y, dind, bv.y);
    acc.z = fmaf(ae.z, dind, bv.z);
    acc.w = fmaf(ae.w, dind, bv.w);
    *(float4*)(out + (size_t)d * 64 + l * 4) = acc;
}

// ---------------- launch: gemm1 forked, CSR on default ----------------
extern "C" void kernel_launch(void* const* d_in, const int* in_sizes, int n_in,
                              void* d_out, int out_size) {
    const float* x  = (const float*)d_in[0];
    const int*   ei = (const int*)d_in[1];
    const float* W1 = (const float*)d_in[2];
    const float* b1 = (const float*)d_in[3];
    const float* W2 = (const float*)d_in[4];
    const float* b2 = (const float*)d_in[5];
    const int* src = ei;
    const int* dst = ei + NE;
    float* out = (float*)d_out;

    static cudaStream_t sB = nullptr;
    static cudaEvent_t evRoot = nullptr, evB = nullptr;
    if (sB == nullptr) {
        cudaStreamCreateWithFlags(&sB, cudaStreamNonBlocking);
        cudaEventCreateWithFlags(&evRoot, cudaEventDisableTiming);
        cudaEventCreateWithFlags(&evB, cudaEventDisableTiming);
    }

    cudaEventRecord(evRoot, 0);
    cudaStreamWaitEvent(sB, evRoot, 0);

    // stream B: GEMM1 (fp16 tensor cores) — hidden under CSR build
    k_gemm1<<<(NN + 127) / 128, 256, 0, sB>>>(x, W1);
    cudaEventRecord(evB, sB);

    // default stream: CSR build
    k_zero<<<98, 256>>>();
    k_deg_count<<<(NE / 4 + 511) / 512, 512>>>(dst);
    k_csr_scan<<<NBLK, 256>>>();
    k_fill<<<(NE / 4 + 511) / 512, 512>>>(src, dst);

    cudaStreamWaitEvent(0, evB, 0);

    k_agg1<<<(NN * 32 + 255) / 256, 256>>>(b1);       // + relu + dropout (threefry fused)
    k_gemm2<<<(NN + 127) / 128, 256>>>(W2);
    k_agg2<<<(NN * 16 + 255) / 256, 256>>>(b2, out);
}

// round 14
// speedup vs baseline: 1.1209x; 1.0148x over previous
#include <cuda_runtime.h>
#include <cuda_fp16.h>
#include <cstdint>

#define NN 100000
#define NE 1600000
#define FH 128
#define FO 64
#define NBLK 391             // ceil(NN/256)

__device__ int      g_dege[NN];      // real in-degree (no self loop)
__device__ float    g_dinv[NN];
__device__ int      g_off[NN + 1];
__device__ int      g_cur[NN];
__device__ int2     g_edge[NE];      // {src, bitcast(dinv[src])} per CSR slot
__device__ unsigned long long g_stat[NBLK];  // decoupled-lookback state
__device__ __half   g_h1[(size_t)NN * FH];   // fp16, unscaled
__device__ __half   g_agg[(size_t)NN * FH];  // fp16 (GEMM2 input, post relu+dropout)
__device__ __half   g_h2[(size_t)NN * FO];   // fp16, pre-scaled by dinv[row]

// ---------------- zero (degrees + scan state) ----------------
__global__ void k_zero() {
    int i = blockIdx.x * blockDim.x + threadIdx.x;   // 25088 threads
    if (i < NN / 4) *(int4*)(g_dege + i * 4) = make_int4(0, 0, 0, 0);
    if (i < NBLK) g_stat[i] = 0ULL;
}

// ---------------- degree count: 4 edges per thread, RED (no return) ----------------
__device__ __forceinline__ void red_add1(int* p) {
    asm volatile("red.global.add.s32 [%0], 1;" :: "l"(p) : "memory");
}
__global__ void __launch_bounds__(512) k_deg_count(const int* __restrict__ dst) {
    int t = blockIdx.x * blockDim.x + threadIdx.x;   // NE/4 threads
    if (t >= NE / 4) return;
    int4 d = __ldg((const int4*)dst + t);
    red_add1(&g_dege[d.x]);
    red_add1(&g_dege[d.y]);
    red_add1(&g_dege[d.z]);
    red_add1(&g_dege[d.w]);
}

// ---------------- CSR offsets: single-kernel decoupled-lookback scan ----------------
__global__ void __launch_bounds__(256) k_csr_scan() {
    __shared__ int sh[256];
    __shared__ int exc_sh;
    const int b = blockIdx.x, t = threadIdx.x;
    const int i = b * 256 + t;
    int d = (i < NN) ? g_dege[i] : 0;

    sh[t] = d;
    __syncthreads();
#pragma unroll
    for (int o = 1; o < 256; o <<= 1) {
        int v = (t >= o) ? sh[t - o] : 0;
        __syncthreads();
        sh[t] += v;
        __syncthreads();
    }
    const unsigned blocksum = (unsigned)sh[255];

    if (b == 0) {
        if (t == 0) {
            atomicExch(&g_stat[0], (2ULL << 32) | blocksum);
            exc_sh = 0;
        }
    } else if (t < 32) {
        if (t == 0) atomicExch(&g_stat[b], (1ULL << 32) | blocksum);
        __syncwarp();
        unsigned running = 0;
        int base = b - 1;
        while (true) {
            int p = base - t;
            unsigned long long s;
            if (p >= 0) {
                const volatile unsigned long long* ps =
                    (const volatile unsigned long long*)(g_stat + p);
                do { s = *ps; } while ((unsigned)(s >> 32) == 0u);
            } else {
                s = (2ULL << 32);
            }
            unsigned ballot = __ballot_sync(0xffffffffu, (unsigned)(s >> 32) == 2u);
            unsigned val = (unsigned)s;
            unsigned contrib;
            bool done = (ballot != 0);
            if (done) {
                int firstp = __ffs(ballot) - 1;
                contrib = (t <= firstp) ? val : 0u;
            } else {
                contrib = val;
            }
#pragma unroll
            for (int o = 16; o > 0; o >>= 1)
                contrib += __shfl_down_sync(0xffffffffu, contrib, o);
            if (t == 0) running += contrib;
            if (done) break;
            base -= 32;
        }
        if (t == 0) {
            atomicExch(&g_stat[b], (2ULL << 32) | (blocksum + running));
            exc_sh = (int)running;
        }
    }
    __syncthreads();

    if (i < NN) {
        int off = exc_sh + sh[t] - d;   // exclusive
        g_off[i] = off;
        g_cur[i] = off;
        g_dinv[i] = rsqrtf((float)(d + 1));   // +1 self loop
        if (i == NN - 1) g_off[NN] = off + d;
    }
}

// ---------------- fill: 4 edges per thread ----------------
__global__ void __launch_bounds__(512) k_fill(const int* __restrict__ src,
                                              const int* __restrict__ dst) {
    int t = blockIdx.x * blockDim.x + threadIdx.x;   // NE/4 threads
    if (t >= NE / 4) return;
    int4 s4 = __ldg((const int4*)src + t);
    int4 d4 = __ldg((const int4*)dst + t);
#pragma unroll
    for (int j = 0; j < 4; j++) {
        int s = (j == 0) ? s4.x : (j == 1) ? s4.y : (j == 2) ? s4.z : s4.w;
        int d = (j == 0) ? d4.x : (j == 1) ? d4.y : (j == 2) ? d4.z : d4.w;
        int slot = atomicAdd(&g_cur[d], 1);
        g_edge[slot] = make_int2(s, __float_as_int(__ldg(g_dinv + s)));
    }
}

// ---------------- JAX threefry2x32 (partitionable path) ----------------
__device__ __forceinline__ uint2 threefry2x32_0_42(unsigned x0, unsigned x1) {
    const unsigned ks0 = 0u, ks1 = 42u, ks2 = 0u ^ 42u ^ 0x1BD11BDAu;
    x0 += ks0; x1 += ks1;
#define TF_R(r) { x0 += x1; x1 = __funnelshift_l(x1, x1, (r)); x1 ^= x0; }
    TF_R(13) TF_R(15) TF_R(26) TF_R(6)
    x0 += ks1; x1 += ks2 + 1u;
    TF_R(17) TF_R(29) TF_R(16) TF_R(24)
    x0 += ks2; x1 += ks0 + 2u;
    TF_R(13) TF_R(15) TF_R(26) TF_R(6)
    x0 += ks0; x1 += ks1 + 3u;
    TF_R(17) TF_R(29) TF_R(16) TF_R(24)
    x0 += ks1; x1 += ks2 + 4u;
    TF_R(13) TF_R(15) TF_R(26) TF_R(6)
    x0 += ks2; x1 += ks0 + 5u;
#undef TF_R
    return make_uint2(x0, x1);
}
__device__ __forceinline__ float drop_mul(unsigned i) {
    uint2 o = threefry2x32_0_42(0u, i);
    return ((int)(o.x ^ o.y) >= 0) ? 2.f : 0.f;
}

// ---------------- fp16 tensor-core GEMM: C[NN x BN] = A[NN x 128] * W[128 x BN] ----------------
__device__ __forceinline__ void mma_f16(float* c, const uint32_t* a, uint32_t b0, uint32_t b1) {
    asm volatile(
        "mma.sync.aligned.m16n8k16.row.col.f32.f16.f16.f32 "
        "{%0,%1,%2,%3}, {%4,%5,%6,%7}, {%8,%9}, {%0,%1,%2,%3};\n"
        : "+f"(c[0]), "+f"(c[1]), "+f"(c[2]), "+f"(c[3])
        : "r"(a[0]), "r"(a[1]), "r"(a[2]), "r"(a[3]), "r"(b0), "r"(b1));
}

template <int BN, bool A_HALF, bool SCALE>
__device__ __forceinline__ void gemm_f16_body(const void* __restrict__ Aptr,
                                              const float* __restrict__ W,
                                              __half* __restrict__ C) {
    __shared__ uint32_t As[128][36];
    __shared__ uint32_t Wt[BN][36];
    const int tid = threadIdx.x;
    const int lane = tid & 31, wid = tid >> 5;
    const int warp_m = wid & 3, warp_n = wid >> 2;
    const int row0 = blockIdx.x * 128;
    constexpr int WN = BN / 2;
    constexpr int TN = WN / 8;

    float c[2][TN][4];
#pragma unroll
    for (int i = 0; i < 2; i++)
#pragma unroll
        for (int j = 0; j < TN; j++)
#pragma unroll
            for (int q = 0; q < 4; q++) c[i][j][q] = 0.f;

    for (int k0 = 0; k0 < 128; k0 += 64) {
        if (A_HALF) {
            const uint4* Ab = (const uint4*)Aptr;
#pragma unroll
            for (int it = 0; it < 4; it++) {
                int idx = tid + it * 256;
                int r = idx >> 3, u = idx & 7;
                int gr = row0 + r; if (gr >= NN) gr = 0;
                uint4 v = __ldg(Ab + (size_t)gr * 16 + (k0 >> 3) + u);
                *(uint4*)&As[r][u * 4] = v;
            }
        } else {
            const float4* Af = (const float4*)Aptr;
#pragma unroll
            for (int it = 0; it < 8; it++) {
                int idx = tid + it * 256;
                int r = idx >> 4, u = idx & 15;
                int gr = row0 + r; if (gr >= NN) gr = 0;
                float4 v = __ldg(Af + (size_t)gr * 32 + (k0 >> 2) + u);
                half2 h0 = __floats2half2_rn(v.x, v.y);
                half2 h1 = __floats2half2_rn(v.z, v.w);
                As[r][u * 2 + 0] = *(uint32_t*)&h0;
                As[r][u * 2 + 1] = *(uint32_t*)&h1;
            }
        }
        constexpr int WIT = (32 * BN) / 256;
#pragma unroll
        for (int it = 0; it < WIT; it++) {
            int idx = tid + it * 256;
            int n = idx % BN, k2 = idx / BN;
            half2 h = __floats2half2_rn(__ldg(W + (size_t)(k0 + 2 * k2) * BN + n),
                                        __ldg(W + (size_t)(k0 + 2 * k2 + 1) * BN + n));
            Wt[n][k2] = *(uint32_t*)&h;
        }
        __syncthreads();

#pragma unroll
        for (int kk = 0; kk < 4; kk++) {
            const int K2 = kk * 8;
            const int ar = warp_m * 32 + (lane >> 2);
            uint32_t a[2][4];
#pragma unroll
            for (int tm = 0; tm < 2; tm++) {
                a[tm][0] = As[ar + tm * 16][K2 + (lane & 3)];
                a[tm][1] = As[ar + tm * 16 + 8][K2 + (lane & 3)];
                a[tm][2] = As[ar + tm * 16][K2 + 4 + (lane & 3)];
                a[tm][3] = As[ar + tm * 16 + 8][K2 + 4 + (lane & 3)];
            }
#pragma unroll
            for (int tn = 0; tn < TN; tn++) {
                int bn = warp_n * WN + tn * 8 + (lane >> 2);
                uint32_t b0 = Wt[bn][K2 + (lane & 3)];
                uint32_t b1 = Wt[bn][K2 + 4 + (lane & 3)];
                mma_f16(c[0][tn], a[0], b0, b1);
                mma_f16(c[1][tn], a[1], b0, b1);
            }
        }
        __syncthreads();
    }

#pragma unroll
    for (int tm = 0; tm < 2; tm++) {
        int rbase = row0 + warp_m * 32 + tm * 16 + (lane >> 2);
#pragma unroll
        for (int half = 0; half < 2; half++) {
            int rr = rbase + half * 8;
            if (rr < NN) {
                float sc = SCALE ? __ldg(g_dinv + rr) : 1.f;
#pragma unroll
                for (int tn = 0; tn < TN; tn++) {
                    int n = warp_n * WN + tn * 8 + 2 * (lane & 3);
                    *(half2*)(C + (size_t)rr * BN + n) =
                        __floats2half2_rn(c[tm][tn][2 * half] * sc,
                                          c[tm][tn][2 * half + 1] * sc);
                }
            }
        }
    }
}

__global__ void __launch_bounds__(256) k_gemm1(const float* __restrict__ A,
                                               const float* __restrict__ W) {
    gemm_f16_body<128, false, false>(A, W, g_h1);
}
__global__ void __launch_bounds__(256) k_gemm2(const float* __restrict__ W) {
    gemm_f16_body<64, true, true>(g_agg, W, g_h2);
}

// ---------------- layer-1 aggregation: warp per node, shfl-distributed edges ----------------
__device__ __forceinline__ void acc_h4(float4& ae, uint2 u, float w) {
    float2 f0 = __half22float2(*reinterpret_cast<half2*>(&u.x));
    float2 f1 = __half22float2(*reinterpret_cast<half2*>(&u.y));
    ae.x = fmaf(f0.x, w, ae.x); ae.y = fmaf(f0.y, w, ae.y);
    ae.z = fmaf(f1.x, w, ae.z); ae.w = fmaf(f1.y, w, ae.w);
}

__global__ void __launch_bounds__(256) k_agg1(const float* __restrict__ b1) {
    int d = (blockIdx.x * 256 + threadIdx.x) >> 5;
    if (d >= NN) return;
    int lane = threadIdx.x & 31;
    float dind = __ldg(g_dinv + d);

    const uint2* hb = (const uint2*)g_h1;
    float4 ae = make_float4(0.f, 0.f, 0.f, 0.f);
    acc_h4(ae, __ldg(hb + (size_t)d * 32 + lane), dind);   // self term

    int beg = __ldg(g_off + d), end = __ldg(g_off + d + 1);
    for (int b0 = beg; b0 < end; b0 += 32) {
        // one coalesced load covers up to 32 edge records for the warp
        int idx = b0 + lane;
        int2 e = (idx < end) ? __ldg(g_edge + idx) : make_int2(0, 0);
        int m = end - b0; if (m > 32) m = 32;
        int j = 0;
        for (; j + 4 <= m; j += 4) {
            int s0 = __shfl_sync(0xffffffffu, e.x, j + 0);
            int s1 = __shfl_sync(0xffffffffu, e.x, j + 1);
            int s2 = __shfl_sync(0xffffffffu, e.x, j + 2);
            int s3 = __shfl_sync(0xffffffffu, e.x, j + 3);
            int w0 = __shfl_sync(0xffffffffu, e.y, j + 0);
            int w1 = __shfl_sync(0xffffffffu, e.y, j + 1);
            int w2 = __shfl_sync(0xffffffffu, e.y, j + 2);
            int w3 = __shfl_sync(0xffffffffu, e.y, j + 3);
            uint2 u0 = __ldg(hb + (size_t)s0 * 32 + lane);
            uint2 u1 = __ldg(hb + (size_t)s1 * 32 + lane);
            uint2 u2 = __ldg(hb + (size_t)s2 * 32 + lane);
            uint2 u3 = __ldg(hb + (size_t)s3 * 32 + lane);
            acc_h4(ae, u0, __int_as_float(w0));
            acc_h4(ae, u1, __int_as_float(w1));
            acc_h4(ae, u2, __int_as_float(w2));
            acc_h4(ae, u3, __int_as_float(w3));
        }
        for (; j < m; j++) {
            int s = __shfl_sync(0xffffffffu, e.x, j);
            int w = __shfl_sync(0xffffffffu, e.y, j);
            acc_h4(ae, __ldg(hb + (size_t)s * 32 + lane), __int_as_float(w));
        }
    }

    int f = lane * 4;
    float4 bv = __ldg((const float4*)(b1 + f));
    unsigned base = (unsigned)d * 128u + (unsigned)f;
    float m0 = drop_mul(base + 0), m1 = drop_mul(base + 1);
    float m2 = drop_mul(base + 2), m3 = drop_mul(base + 3);
    float4 acc;
    acc.x = fmaxf(fmaf(ae.x, dind, bv.x), 0.f) * m0;
    acc.y = fmaxf(fmaf(ae.y, dind, bv.y), 0.f) * m1;
    acc.z = fmaxf(fmaf(ae.z, dind, bv.z), 0.f) * m2;
    acc.w = fmaxf(fmaf(ae.w, dind, bv.w), 0.f) * m3;

    half2 h0 = __floats2half2_rn(acc.x, acc.y);
    half2 h1 = __floats2half2_rn(acc.z, acc.w);
    uint2 st = make_uint2(*(uint32_t*)&h0, *(uint32_t*)&h1);
    *(uint2*)(g_agg + (size_t)d * 128 + f) = st;
}

// ---------------- layer-2 aggregation: half warp per node, shfl-distributed edges ----------------
__global__ void __launch_bounds__(256) k_agg2(const float* __restrict__ b2,
                                              float* __restrict__ out) {
    int t = blockIdx.x * 256 + threadIdx.x;
    int d = t >> 4;
    if (d >= NN) return;
    int l = t & 15;
    float dind = __ldg(g_dinv + d);

    const uint2* hb = (const uint2*)g_h2;
    float4 ae = make_float4(0.f, 0.f, 0.f, 0.f);
    acc_h4(ae, __ldg(hb + (size_t)d * 16 + l), 1.f);   // self term (pre-scaled)

    int beg = __ldg(g_off + d), end = __ldg(g_off + d + 1);
    // half-warp (16 lanes) coalesced edge fetch; shfl within the 16-lane group
    for (int b0 = beg; b0 < end; b0 += 16) {
        int idx = b0 + l;
        int s_own = (idx < end) ? __ldg(&g_edge[idx].x) : 0;
        int m = end - b0; if (m > 16) m = 16;
        int j = 0;
        for (; j + 4 <= m; j += 4) {
            int s0 = __shfl_sync(0xffffffffu, s_own, ((t & 16) | (j + 0)), 32);
            int s1 = __shfl_sync(0xffffffffu, s_own, ((t & 16) | (j + 1)), 32);
            int s2 = __shfl_sync(0xffffffffu, s_own, ((t & 16) | (j + 2)), 32);
            int s3 = __shfl_sync(0xffffffffu, s_own, ((t & 16) | (j + 3)), 32);
            uint2 u0 = __ldg(hb + (size_t)s0 * 16 + l);
            uint2 u1 = __ldg(hb + (size_t)s1 * 16 + l);
            uint2 u2 = __ldg(hb + (size_t)s2 * 16 + l);
            uint2 u3 = __ldg(hb + (size_t)s3 * 16 + l);
            acc_h4(ae, u0, 1.f); acc_h4(ae, u1, 1.f);
            acc_h4(ae, u2, 1.f); acc_h4(ae, u3, 1.f);
        }
        for (; j < m; j++) {
            int s = __shfl_sync(0xffffffffu, s_own, ((t & 16) | j), 32);
            acc_h4(ae, __ldg(hb + (size_t)s * 16 + l), 1.f);
        }
    }

    float4 bv = __ldg((const float4*)(b2 + l * 4));
    float4 acc;
    acc.x = fmaf(ae.x, dind, bv.x);
    acc.y = fmaf(ae.y, dind, bv.y);
    acc.z = fmaf(ae.z, dind, bv.z);
    acc.w = fmaf(ae.w, dind, bv.w);
    *(float4*)(out + (size_t)d * 64 + l * 4) = acc;
}

// ---------------- launch: gemm1 forked, CSR on default ----------------
extern "C" void kernel_launch(void* const* d_in, const int* in_sizes, int n_in,
                              void* d_out, int out_size) {
    const float* x  = (const float*)d_in[0];
    const int*   ei = (const int*)d_in[1];
    const float* W1 = (const float*)d_in[2];
    const float* b1 = (const float*)d_in[3];
    const float* W2 = (const float*)d_in[4];
    const float* b2 = (const float*)d_in[5];
    const int* src = ei;
    const int* dst = ei + NE;
    float* out = (float*)d_out;

    static cudaStream_t sB = nullptr;
    static cudaEvent_t evRoot = nullptr, evB = nullptr;
    if (sB == nullptr) {
        cudaStreamCreateWithFlags(&sB, cudaStreamNonBlocking);
        cudaEventCreateWithFlags(&evRoot, cudaEventDisableTiming);
        cudaEventCreateWithFlags(&evB, cudaEventDisableTiming);
    }

    cudaEventRecord(evRoot, 0);
    cudaStreamWaitEvent(sB, evRoot, 0);

    // stream B: GEMM1 (fp16 tensor cores) — hidden under CSR build
    k_gemm1<<<(NN + 127) / 128, 256, 0, sB>>>(x, W1);
    cudaEventRecord(evB, sB);

    // default stream: CSR build
    k_zero<<<98, 256>>>();
    k_deg_count<<<(NE / 4 + 511) / 512, 512>>>(dst);
    k_csr_scan<<<NBLK, 256>>>();
    k_fill<<<(NE / 4 + 511) / 512, 512>>>(src, dst);

    cudaStreamWaitEvent(0, evB, 0);

    k_agg1<<<(NN * 32 + 255) / 256, 256>>>(b1);       // + relu + dropout (threefry fused)
    k_gemm2<<<(NN + 127) / 128, 256>>>(W2);
    k_agg2<<<(NN * 16 + 255) / 256, 256>>>(b2, out);
}

// round 15
// speedup vs baseline: 1.1867x; 1.0587x over previous
#include <cuda_runtime.h>
#include <cuda_fp16.h>
#include <cstdint>

#define NN 100000
#define NE 1600000
#define FH 128
#define FO 64
#define NBLK 391             // ceil(NN/256)
#define CHUNK0 50048         // 391 * 128 (gemm block aligned)

__device__ int      g_dege[NN];      // real in-degree (no self loop)
__device__ float    g_dinv[NN];
__device__ int      g_off[NN + 1];
__device__ int      g_cur[NN];
__device__ int2     g_edge[NE];      // {src, bitcast(dinv[src])} per CSR slot
__device__ unsigned long long g_stat[NBLK];  // decoupled-lookback state
__device__ __half   g_h1[(size_t)NN * FH];   // fp16, unscaled
__device__ __half   g_agg[(size_t)NN * FH];  // fp16 (GEMM2 input, post relu+dropout)
__device__ __half   g_h2[(size_t)NN * FO];   // fp16, pre-scaled by dinv[row]

// ---------------- zero (degrees + scan state) ----------------
__global__ void k_zero() {
    int i = blockIdx.x * blockDim.x + threadIdx.x;   // 25088 threads
    if (i < NN / 4) *(int4*)(g_dege + i * 4) = make_int4(0, 0, 0, 0);
    if (i < NBLK) g_stat[i] = 0ULL;
}

// ---------------- degree count: 8 edges per thread, RED (no return) ----------------
__device__ __forceinline__ void red_add1(int* p) {
    asm volatile("red.global.add.s32 [%0], 1;" :: "l"(p) : "memory");
}
__global__ void __launch_bounds__(512) k_deg_count(const int* __restrict__ dst) {
    int t = blockIdx.x * blockDim.x + threadIdx.x;   // NE/8 threads
    if (t >= NE / 8) return;
    int4 d0 = __ldg((const int4*)dst + 2 * t);
    int4 d1 = __ldg((const int4*)dst + 2 * t + 1);
    red_add1(&g_dege[d0.x]); red_add1(&g_dege[d0.y]);
    red_add1(&g_dege[d0.z]); red_add1(&g_dege[d0.w]);
    red_add1(&g_dege[d1.x]); red_add1(&g_dege[d1.y]);
    red_add1(&g_dege[d1.z]); red_add1(&g_dege[d1.w]);
}

// ---------------- CSR offsets: single-kernel decoupled-lookback scan ----------------
__global__ void __launch_bounds__(256) k_csr_scan() {
    __shared__ int sh[256];
    __shared__ int exc_sh;
    const int b = blockIdx.x, t = threadIdx.x;
    const int i = b * 256 + t;
    int d = (i < NN) ? g_dege[i] : 0;

    sh[t] = d;
    __syncthreads();
#pragma unroll
    for (int o = 1; o < 256; o <<= 1) {
        int v = (t >= o) ? sh[t - o] : 0;
        __syncthreads();
        sh[t] += v;
        __syncthreads();
    }
    const unsigned blocksum = (unsigned)sh[255];

    if (b == 0) {
        if (t == 0) {
            atomicExch(&g_stat[0], (2ULL << 32) | blocksum);
            exc_sh = 0;
        }
    } else if (t < 32) {
        if (t == 0) atomicExch(&g_stat[b], (1ULL << 32) | blocksum);
        __syncwarp();
        unsigned running = 0;
        int base = b - 1;
        while (true) {
            int p = base - t;
            unsigned long long s;
            if (p >= 0) {
                const volatile unsigned long long* ps =
                    (const volatile unsigned long long*)(g_stat + p);
                do { s = *ps; } while ((unsigned)(s >> 32) == 0u);
            } else {
                s = (2ULL << 32);
            }
            unsigned ballot = __ballot_sync(0xffffffffu, (unsigned)(s >> 32) == 2u);
            unsigned val = (unsigned)s;
            unsigned contrib;
            bool done = (ballot != 0);
            if (done) {
                int firstp = __ffs(ballot) - 1;
                contrib = (t <= firstp) ? val : 0u;
            } else {
                contrib = val;
            }
#pragma unroll
            for (int o = 16; o > 0; o >>= 1)
                contrib += __shfl_down_sync(0xffffffffu, contrib, o);
            if (t == 0) running += contrib;
            if (done) break;
            base -= 32;
        }
        if (t == 0) {
            atomicExch(&g_stat[b], (2ULL << 32) | (blocksum + running));
            exc_sh = (int)running;
        }
    }
    __syncthreads();

    if (i < NN) {
        int off = exc_sh + sh[t] - d;   // exclusive
        g_off[i] = off;
        g_cur[i] = off;
        g_dinv[i] = rsqrtf((float)(d + 1));   // +1 self loop
        if (i == NN - 1) g_off[NN] = off + d;
    }
}

// ---------------- fill: 4 edges per thread ----------------
__global__ void __launch_bounds__(512) k_fill(const int* __restrict__ src,
                                              const int* __restrict__ dst) {
    int t = blockIdx.x * blockDim.x + threadIdx.x;   // NE/4 threads
    if (t >= NE / 4) return;
    int4 s4 = __ldg((const int4*)src + t);
    int4 d4 = __ldg((const int4*)dst + t);
#pragma unroll
    for (int j = 0; j < 4; j++) {
        int s = (j == 0) ? s4.x : (j == 1) ? s4.y : (j == 2) ? s4.z : s4.w;
        int d = (j == 0) ? d4.x : (j == 1) ? d4.y : (j == 2) ? d4.z : d4.w;
        int slot = atomicAdd(&g_cur[d], 1);
        g_edge[slot] = make_int2(s, __float_as_int(__ldg(g_dinv + s)));
    }
}

// ---------------- JAX threefry2x32 (partitionable path) ----------------
__device__ __forceinline__ uint2 threefry2x32_0_42(unsigned x0, unsigned x1) {
    const unsigned ks0 = 0u, ks1 = 42u, ks2 = 0u ^ 42u ^ 0x1BD11BDAu;
    x0 += ks0; x1 += ks1;
#define TF_R(r) { x0 += x1; x1 = __funnelshift_l(x1, x1, (r)); x1 ^= x0; }
    TF_R(13) TF_R(15) TF_R(26) TF_R(6)
    x0 += ks1; x1 += ks2 + 1u;
    TF_R(17) TF_R(29) TF_R(16) TF_R(24)
    x0 += ks2; x1 += ks0 + 2u;
    TF_R(13) TF_R(15) TF_R(26) TF_R(6)
    x0 += ks0; x1 += ks1 + 3u;
    TF_R(17) TF_R(29) TF_R(16) TF_R(24)
    x0 += ks1; x1 += ks2 + 4u;
    TF_R(13) TF_R(15) TF_R(26) TF_R(6)
    x0 += ks2; x1 += ks0 + 5u;
#undef TF_R
    return make_uint2(x0, x1);
}
__device__ __forceinline__ float drop_mul(unsigned i) {
    uint2 o = threefry2x32_0_42(0u, i);
    return ((int)(o.x ^ o.y) >= 0) ? 2.f : 0.f;
}

// ---------------- fp16 tensor-core GEMM: C[rows x BN] = A[rows x 128] * W[128 x BN] ----------------
__device__ __forceinline__ void mma_f16(float* c, const uint32_t* a, uint32_t b0, uint32_t b1) {
    asm volatile(
        "mma.sync.aligned.m16n8k16.row.col.f32.f16.f16.f32 "
        "{%0,%1,%2,%3}, {%4,%5,%6,%7}, {%8,%9}, {%0,%1,%2,%3};\n"
        : "+f"(c[0]), "+f"(c[1]), "+f"(c[2]), "+f"(c[3])
        : "r"(a[0]), "r"(a[1]), "r"(a[2]), "r"(a[3]), "r"(b0), "r"(b1));
}

template <int BN, bool A_HALF, bool SCALE>
__device__ __forceinline__ void gemm_f16_body(const void* __restrict__ Aptr,
                                              const float* __restrict__ W,
                                              __half* __restrict__ C,
                                              int row_base) {
    __shared__ uint32_t As[128][36];
    __shared__ uint32_t Wt[BN][36];
    const int tid = threadIdx.x;
    const int lane = tid & 31, wid = tid >> 5;
    const int warp_m = wid & 3, warp_n = wid >> 2;
    const int row0 = row_base + blockIdx.x * 128;
    constexpr int WN = BN / 2;
    constexpr int TN = WN / 8;

    float c[2][TN][4];
#pragma unroll
    for (int i = 0; i < 2; i++)
#pragma unroll
        for (int j = 0; j < TN; j++)
#pragma unroll
            for (int q = 0; q < 4; q++) c[i][j][q] = 0.f;

    for (int k0 = 0; k0 < 128; k0 += 64) {
        if (A_HALF) {
            const uint4* Ab = (const uint4*)Aptr;
#pragma unroll
            for (int it = 0; it < 4; it++) {
                int idx = tid + it * 256;
                int r = idx >> 3, u = idx & 7;
                int gr = row0 + r; if (gr >= NN) gr = 0;
                uint4 v = __ldg(Ab + (size_t)gr * 16 + (k0 >> 3) + u);
                *(uint4*)&As[r][u * 4] = v;
            }
        } else {
            const float4* Af = (const float4*)Aptr;
#pragma unroll
            for (int it = 0; it < 8; it++) {
                int idx = tid + it * 256;
                int r = idx >> 4, u = idx & 15;
                int gr = row0 + r; if (gr >= NN) gr = 0;
                float4 v = __ldg(Af + (size_t)gr * 32 + (k0 >> 2) + u);
                half2 h0 = __floats2half2_rn(v.x, v.y);
                half2 h1 = __floats2half2_rn(v.z, v.w);
                As[r][u * 2 + 0] = *(uint32_t*)&h0;
                As[r][u * 2 + 1] = *(uint32_t*)&h1;
            }
        }
        constexpr int WIT = (32 * BN) / 256;
#pragma unroll
        for (int it = 0; it < WIT; it++) {
            int idx = tid + it * 256;
            int n = idx % BN, k2 = idx / BN;
            half2 h = __floats2half2_rn(__ldg(W + (size_t)(k0 + 2 * k2) * BN + n),
                                        __ldg(W + (size_t)(k0 + 2 * k2 + 1) * BN + n));
            Wt[n][k2] = *(uint32_t*)&h;
        }
        __syncthreads();

#pragma unroll
        for (int kk = 0; kk < 4; kk++) {
            const int K2 = kk * 8;
            const int ar = warp_m * 32 + (lane >> 2);
            uint32_t a[2][4];
#pragma unroll
            for (int tm = 0; tm < 2; tm++) {
                a[tm][0] = As[ar + tm * 16][K2 + (lane & 3)];
                a[tm][1] = As[ar + tm * 16 + 8][K2 + (lane & 3)];
                a[tm][2] = As[ar + tm * 16][K2 + 4 + (lane & 3)];
                a[tm][3] = As[ar + tm * 16 + 8][K2 + 4 + (lane & 3)];
            }
#pragma unroll
            for (int tn = 0; tn < TN; tn++) {
                int bn = warp_n * WN + tn * 8 + (lane >> 2);
                uint32_t b0 = Wt[bn][K2 + (lane & 3)];
                uint32_t b1 = Wt[bn][K2 + 4 + (lane & 3)];
                mma_f16(c[0][tn], a[0], b0, b1);
                mma_f16(c[1][tn], a[1], b0, b1);
            }
        }
        __syncthreads();
    }

#pragma unroll
    for (int tm = 0; tm < 2; tm++) {
        int rbase = row0 + warp_m * 32 + tm * 16 + (lane >> 2);
#pragma unroll
        for (int half = 0; half < 2; half++) {
            int rr = rbase + half * 8;
            if (rr < NN) {
                float sc = SCALE ? __ldg(g_dinv + rr) : 1.f;
#pragma unroll
                for (int tn = 0; tn < TN; tn++) {
                    int n = warp_n * WN + tn * 8 + 2 * (lane & 3);
                    *(half2*)(C + (size_t)rr * BN + n) =
                        __floats2half2_rn(c[tm][tn][2 * half] * sc,
                                          c[tm][tn][2 * half + 1] * sc);
                }
            }
        }
    }
}

__global__ void __launch_bounds__(256) k_gemm1(const float* __restrict__ A,
                                               const float* __restrict__ W) {
    gemm_f16_body<128, false, false>(A, W, g_h1, 0);
}
__global__ void __launch_bounds__(256) k_gemm2(const float* __restrict__ W, int row_base) {
    gemm_f16_body<64, true, true>(g_agg, W, g_h2, row_base);
}

// ---------------- layer-1 aggregation: warp per node, fused relu+dropout (node range) ----------------
__device__ __forceinline__ void acc_h4(float4& ae, uint2 u, float w) {
    float2 f0 = __half22float2(*reinterpret_cast<half2*>(&u.x));
    float2 f1 = __half22float2(*reinterpret_cast<half2*>(&u.y));
    ae.x = fmaf(f0.x, w, ae.x); ae.y = fmaf(f0.y, w, ae.y);
    ae.z = fmaf(f1.x, w, ae.z); ae.w = fmaf(f1.y, w, ae.w);
}

__global__ void __launch_bounds__(256) k_agg1(const float* __restrict__ b1,
                                              int node_base, int node_cnt) {
    int d = node_base + ((blockIdx.x * 256 + threadIdx.x) >> 5);
    if (d >= node_base + node_cnt) return;
    int lane = threadIdx.x & 31;
    float dind = __ldg(g_dinv + d);

    const uint2* hb = (const uint2*)g_h1;
    float4 ae = make_float4(0.f, 0.f, 0.f, 0.f);
    acc_h4(ae, __ldg(hb + (size_t)d * 32 + lane), dind);   // self term

    int beg = __ldg(g_off + d), end = __ldg(g_off + d + 1);
    int i = beg;
    for (; i + 4 <= end; i += 4) {
        int2 e0 = __ldg(g_edge + i + 0);
        int2 e1 = __ldg(g_edge + i + 1);
        int2 e2 = __ldg(g_edge + i + 2);
        int2 e3 = __ldg(g_edge + i + 3);
        uint2 u0 = __ldg(hb + (size_t)e0.x * 32 + lane);
        uint2 u1 = __ldg(hb + (size_t)e1.x * 32 + lane);
        uint2 u2 = __ldg(hb + (size_t)e2.x * 32 + lane);
        uint2 u3 = __ldg(hb + (size_t)e3.x * 32 + lane);
        acc_h4(ae, u0, __int_as_float(e0.y));
        acc_h4(ae, u1, __int_as_float(e1.y));
        acc_h4(ae, u2, __int_as_float(e2.y));
        acc_h4(ae, u3, __int_as_float(e3.y));
    }
    for (; i < end; i++) {
        int2 e = __ldg(g_edge + i);
        acc_h4(ae, __ldg(hb + (size_t)e.x * 32 + lane), __int_as_float(e.y));
    }

    int f = lane * 4;
    float4 bv = __ldg((const float4*)(b1 + f));
    unsigned base = (unsigned)d * 128u + (unsigned)f;
    float m0 = drop_mul(base + 0), m1 = drop_mul(base + 1);
    float m2 = drop_mul(base + 2), m3 = drop_mul(base + 3);
    float4 acc;
    acc.x = fmaxf(fmaf(ae.x, dind, bv.x), 0.f) * m0;
    acc.y = fmaxf(fmaf(ae.y, dind, bv.y), 0.f) * m1;
    acc.z = fmaxf(fmaf(ae.z, dind, bv.z), 0.f) * m2;
    acc.w = fmaxf(fmaf(ae.w, dind, bv.w), 0.f) * m3;

    half2 h0 = __floats2half2_rn(acc.x, acc.y);
    half2 h1 = __floats2half2_rn(acc.z, acc.w);
    uint2 st = make_uint2(*(uint32_t*)&h0, *(uint32_t*)&h1);
    *(uint2*)(g_agg + (size_t)d * 128 + f) = st;
}

// ---------------- layer-2 aggregation: half warp per node, fp16 gather (pre-scaled) ----------------
__global__ void __launch_bounds__(256) k_agg2(const float* __restrict__ b2,
                                              float* __restrict__ out) {
    int t = blockIdx.x * 256 + threadIdx.x;
    int d = t >> 4;
    if (d >= NN) return;
    int l = t & 15;
    float dind = __ldg(g_dinv + d);

    const uint2* hb = (const uint2*)g_h2;
    float4 ae = make_float4(0.f, 0.f, 0.f, 0.f);
    acc_h4(ae, __ldg(hb + (size_t)d * 16 + l), 1.f);   // self term (pre-scaled)

    int beg = __ldg(g_off + d), end = __ldg(g_off + d + 1);
    int i = beg;
    for (; i + 4 <= end; i += 4) {
        int2 e0 = __ldg(g_edge + i + 0);
        int2 e1 = __ldg(g_edge + i + 1);
        int2 e2 = __ldg(g_edge + i + 2);
        int2 e3 = __ldg(g_edge + i + 3);
        uint2 u0 = __ldg(hb + (size_t)e0.x * 16 + l);
        uint2 u1 = __ldg(hb + (size_t)e1.x * 16 + l);
        uint2 u2 = __ldg(hb + (size_t)e2.x * 16 + l);
        uint2 u3 = __ldg(hb + (size_t)e3.x * 16 + l);
        acc_h4(ae, u0, 1.f); acc_h4(ae, u1, 1.f);
        acc_h4(ae, u2, 1.f); acc_h4(ae, u3, 1.f);
    }
    for (; i < end; i++) {
        int2 e = __ldg(g_edge + i);
        acc_h4(ae, __ldg(hb + (size_t)e.x * 16 + l), 1.f);
    }

    float4 bv = __ldg((const float4*)(b2 + l * 4));
    float4 acc;
    acc.x = fmaf(ae.x, dind, bv.x);
    acc.y = fmaf(ae.y, dind, bv.y);
    acc.z = fmaf(ae.z, dind, bv.z);
    acc.w = fmaf(ae.w, dind, bv.w);
    *(float4*)(out + (size_t)d * 64 + l * 4) = acc;
}

// ---------------- launch: gemm1 forked; agg1/gemm2 2-chunk pipeline ----------------
extern "C" void kernel_launch(void* const* d_in, const int* in_sizes, int n_in,
                              void* d_out, int out_size) {
    const float* x  = (const float*)d_in[0];
    const int*   ei = (const int*)d_in[1];
    const float* W1 = (const float*)d_in[2];
    const float* b1 = (const float*)d_in[3];
    const float* W2 = (const float*)d_in[4];
    const float* b2 = (const float*)d_in[5];
    const int* src = ei;
    const int* dst = ei + NE;
    float* out = (float*)d_out;

    static cudaStream_t sB = nullptr;
    static cudaEvent_t evRoot = nullptr, evB = nullptr;
    static cudaEvent_t evA0 = nullptr, evA1 = nullptr, evG2 = nullptr;
    if (sB == nullptr) {
        cudaStreamCreateWithFlags(&sB, cudaStreamNonBlocking);
        cudaEventCreateWithFlags(&evRoot, cudaEventDisableTiming);
        cudaEventCreateWithFlags(&evB, cudaEventDisableTiming);
        cudaEventCreateWithFlags(&evA0, cudaEventDisableTiming);
        cudaEventCreateWithFlags(&evA1, cudaEventDisableTiming);
        cudaEventCreateWithFlags(&evG2, cudaEventDisableTiming);
    }

    cudaEventRecord(evRoot, 0);
    cudaStreamWaitEvent(sB, evRoot, 0);

    // stream B: GEMM1 (fp16 tensor cores) — hidden under CSR build
    k_gemm1<<<(NN + 127) / 128, 256, 0, sB>>>(x, W1);
    cudaEventRecord(evB, sB);

    // default stream: CSR build
    k_zero<<<98, 256>>>();
    k_deg_count<<<(NE / 8 + 511) / 512, 512>>>(dst);
    k_csr_scan<<<NBLK, 256>>>();
    k_fill<<<(NE / 4 + 511) / 512, 512>>>(src, dst);

    cudaStreamWaitEvent(0, evB, 0);

    // pipeline: agg1(c0); gemm2(c0) on sB overlaps agg1(c1); gemm2(c1); agg2
    const int C0 = CHUNK0, C1 = NN - CHUNK0;
    k_agg1<<<(C0 * 32 + 255) / 256, 256>>>(b1, 0, C0);
    cudaEventRecord(evA0, 0);
    k_agg1<<<(C1 * 32 + 255) / 256, 256>>>(b1, C0, C1);
    cudaEventRecord(evA1, 0);

    cudaStreamWaitEvent(sB, evA0, 0);
    k_gemm2<<<C0 / 128, 256, 0, sB>>>(W2, 0);
    cudaStreamWaitEvent(sB, evA1, 0);
    k_gemm2<<<(C1 + 127) / 128, 256, 0, sB>>>(W2, C0);
    cudaEventRecord(evG2, sB);

    cudaStreamWaitEvent(0, evG2, 0);
    k_agg2<<<(NN * 16 + 255) / 256, 256>>>(b2, out);
}

// round 17
// speedup vs baseline: 1.2009x; 1.0119x over previous
#include <cuda_runtime.h>
#include <cuda_fp16.h>
#include <cstdint>

#define NN 100000
#define NE 1600000
#define FH 128
#define FO 64
#define NBLK 391             // ceil(NN/256)

__device__ int      g_dege[NN];      // zero at kernel_launch entry (invariant, see k_cleanup)
__device__ float    g_dinv[NN];
__device__ int      g_off[NN + 1];
__device__ int      g_cur[NN];
__device__ int2     g_edge[NE];      // {src, bitcast(dinv[src])} per CSR slot
__device__ unsigned long long g_stat[NBLK];  // decoupled-lookback state (zero at entry)
__device__ __half   g_h1[(size_t)NN * FH];   // fp16, unscaled
__device__ __half   g_agg[(size_t)NN * FH];  // fp16 (GEMM2 input, post relu+dropout)
__device__ __half   g_h2[(size_t)NN * FO];   // fp16, pre-scaled by dinv[row]

// ---------------- cleanup: restore zero-invariant OFF the critical path ----------------
__global__ void k_cleanup() {
    int i = blockIdx.x * blockDim.x + threadIdx.x;   // 25088 threads
    if (i < NN / 4) *(int4*)(g_dege + i * 4) = make_int4(0, 0, 0, 0);
    if (i < NBLK) g_stat[i] = 0ULL;
}

// ---------------- degree count: 4 edges per thread, RED (no return) ----------------
__device__ __forceinline__ void red_add1(int* p) {
    asm volatile("red.global.add.s32 [%0], 1;" :: "l"(p) : "memory");
}
__global__ void __launch_bounds__(512) k_deg_count(const int* __restrict__ dst) {
    int t = blockIdx.x * blockDim.x + threadIdx.x;   // NE/4 threads
    if (t >= NE / 4) return;
    int4 d = __ldg((const int4*)dst + t);
    red_add1(&g_dege[d.x]);
    red_add1(&g_dege[d.y]);
    red_add1(&g_dege[d.z]);
    red_add1(&g_dege[d.w]);
}

// ---------------- CSR offsets: single-kernel decoupled-lookback scan ----------------
__global__ void __launch_bounds__(256) k_csr_scan() {
    __shared__ int sh[256];
    __shared__ int exc_sh;
    const int b = blockIdx.x, t = threadIdx.x;
    const int i = b * 256 + t;
    int d = (i < NN) ? g_dege[i] : 0;

    sh[t] = d;
    __syncthreads();
#pragma unroll
    for (int o = 1; o < 256; o <<= 1) {
        int v = (t >= o) ? sh[t - o] : 0;
        __syncthreads();
        sh[t] += v;
        __syncthreads();
    }
    const unsigned blocksum = (unsigned)sh[255];

    if (b == 0) {
        if (t == 0) {
            atomicExch(&g_stat[0], (2ULL << 32) | blocksum);
            exc_sh = 0;
        }
    } else if (t < 32) {
        if (t == 0) atomicExch(&g_stat[b], (1ULL << 32) | blocksum);
        __syncwarp();
        unsigned running = 0;
        int base = b - 1;
        while (true) {
            int p = base - t;
            unsigned long long s;
            if (p >= 0) {
                const volatile unsigned long long* ps =
                    (const volatile unsigned long long*)(g_stat + p);
                do { s = *ps; } while ((unsigned)(s >> 32) == 0u);
            } else {
                s = (2ULL << 32);
            }
            unsigned ballot = __ballot_sync(0xffffffffu, (unsigned)(s >> 32) == 2u);
            unsigned val = (unsigned)s;
            unsigned contrib;
            bool done = (ballot != 0);
            if (done) {
                int firstp = __ffs(ballot) - 1;
                contrib = (t <= firstp) ? val : 0u;
            } else {
                contrib = val;
            }
#pragma unroll
            for (int o = 16; o > 0; o >>= 1)
                contrib += __shfl_down_sync(0xffffffffu, contrib, o);
            if (t == 0) running += contrib;
            if (done) break;
            base -= 32;
        }
        if (t == 0) {
            atomicExch(&g_stat[b], (2ULL << 32) | (blocksum + running));
            exc_sh = (int)running;
        }
    }
    __syncthreads();

    if (i < NN) {
        int off = exc_sh + sh[t] - d;   // exclusive
        g_off[i] = off;
        g_cur[i] = off;
        g_dinv[i] = rsqrtf((float)(d + 1));   // +1 self loop
        if (i == NN - 1) g_off[NN] = off + d;
    }
}

// ---------------- fill: 4 edges per thread ----------------
__global__ void __launch_bounds__(512) k_fill(const int* __restrict__ src,
                                              const int* __restrict__ dst) {
    int t = blockIdx.x * blockDim.x + threadIdx.x;   // NE/4 threads
    if (t >= NE / 4) return;
    int4 s4 = __ldg((const int4*)src + t);
    int4 d4 = __ldg((const int4*)dst + t);
#pragma unroll
    for (int j = 0; j < 4; j++) {
        int s = (j == 0) ? s4.x : (j == 1) ? s4.y : (j == 2) ? s4.z : s4.w;
        int d = (j == 0) ? d4.x : (j == 1) ? d4.y : (j == 2) ? d4.z : d4.w;
        int slot = atomicAdd(&g_cur[d], 1);
        g_edge[slot] = make_int2(s, __float_as_int(__ldg(g_dinv + s)));
    }
}

// ---------------- JAX threefry2x32 (partitionable path) ----------------
__device__ __forceinline__ uint2 threefry2x32_0_42(unsigned x0, unsigned x1) {
    const unsigned ks0 = 0u, ks1 = 42u, ks2 = 0u ^ 42u ^ 0x1BD11BDAu;
    x0 += ks0; x1 += ks1;
#define TF_R(r) { x0 += x1; x1 = __funnelshift_l(x1, x1, (r)); x1 ^= x0; }
    TF_R(13) TF_R(15) TF_R(26) TF_R(6)
    x0 += ks1; x1 += ks2 + 1u;
    TF_R(17) TF_R(29) TF_R(16) TF_R(24)
    x0 += ks2; x1 += ks0 + 2u;
    TF_R(13) TF_R(15) TF_R(26) TF_R(6)
    x0 += ks0; x1 += ks1 + 3u;
    TF_R(17) TF_R(29) TF_R(16) TF_R(24)
    x0 += ks1; x1 += ks2 + 4u;
    TF_R(13) TF_R(15) TF_R(26) TF_R(6)
    x0 += ks2; x1 += ks0 + 5u;
#undef TF_R
    return make_uint2(x0, x1);
}
__device__ __forceinline__ float drop_mul(unsigned i) {
    uint2 o = threefry2x32_0_42(0u, i);
    return ((int)(o.x ^ o.y) >= 0) ? 2.f : 0.f;
}

// ---------------- fp16 tensor-core GEMM: C[NN x BN] = A[NN x 128] * W[128 x BN] ----------------
__device__ __forceinline__ void mma_f16(float* c, const uint32_t* a, uint32_t b0, uint32_t b1) {
    asm volatile(
        "mma.sync.aligned.m16n8k16.row.col.f32.f16.f16.f32 "
        "{%0,%1,%2,%3}, {%4,%5,%6,%7}, {%8,%9}, {%0,%1,%2,%3};\n"
        : "+f"(c[0]), "+f"(c[1]), "+f"(c[2]), "+f"(c[3])
        : "r"(a[0]), "r"(a[1]), "r"(a[2]), "r"(a[3]), "r"(b0), "r"(b1));
}

template <int BN, bool A_HALF, bool SCALE>
__device__ __forceinline__ void gemm_f16_body(const void* __restrict__ Aptr,
                                              const float* __restrict__ W,
                                              __half* __restrict__ C) {
    __shared__ uint32_t As[128][36];
    __shared__ uint32_t Wt[BN][36];
    const int tid = threadIdx.x;
    const int lane = tid & 31, wid = tid >> 5;
    const int warp_m = wid & 3, warp_n = wid >> 2;
    const int row0 = blockIdx.x * 128;
    constexpr int WN = BN / 2;
    constexpr int TN = WN / 8;

    float c[2][TN][4];
#pragma unroll
    for (int i = 0; i < 2; i++)
#pragma unroll
        for (int j = 0; j < TN; j++)
#pragma unroll
            for (int q = 0; q < 4; q++) c[i][j][q] = 0.f;

    for (int k0 = 0; k0 < 128; k0 += 64) {
        if (A_HALF) {
            const uint4* Ab = (const uint4*)Aptr;
#pragma unroll
            for (int it = 0; it < 4; it++) {
                int idx = tid + it * 256;
                int r = idx >> 3, u = idx & 7;
                int gr = row0 + r; if (gr >= NN) gr = 0;
                uint4 v = __ldg(Ab + (size_t)gr * 16 + (k0 >> 3) + u);
                *(uint4*)&As[r][u * 4] = v;
            }
        } else {
            const float4* Af = (const float4*)Aptr;
#pragma unroll
            for (int it = 0; it < 8; it++) {
                int idx = tid + it * 256;
                int r = idx >> 4, u = idx & 15;
                int gr = row0 + r; if (gr >= NN) gr = 0;
                float4 v = __ldg(Af + (size_t)gr * 32 + (k0 >> 2) + u);
                half2 h0 = __floats2half2_rn(v.x, v.y);
                half2 h1 = __floats2half2_rn(v.z, v.w);
                As[r][u * 2 + 0] = *(uint32_t*)&h0;
                As[r][u * 2 + 1] = *(uint32_t*)&h1;
            }
        }
        constexpr int WIT = (32 * BN) / 256;
#pragma unroll
        for (int it = 0; it < WIT; it++) {
            int idx = tid + it * 256;
            int n = idx % BN, k2 = idx / BN;
            half2 h = __floats2half2_rn(__ldg(W + (size_t)(k0 + 2 * k2) * BN + n),
                                        __ldg(W + (size_t)(k0 + 2 * k2 + 1) * BN + n));
            Wt[n][k2] = *(uint32_t*)&h;
        }
        __syncthreads();

#pragma unroll
        for (int kk = 0; kk < 4; kk++) {
            const int K2 = kk * 8;
            const int ar = warp_m * 32 + (lane >> 2);
            uint32_t a[2][4];
#pragma unroll
            for (int tm = 0; tm < 2; tm++) {
                a[tm][0] = As[ar + tm * 16][K2 + (lane & 3)];
                a[tm][1] = As[ar + tm * 16 + 8][K2 + (lane & 3)];
                a[tm][2] = As[ar + tm * 16][K2 + 4 + (lane & 3)];
                a[tm][3] = As[ar + tm * 16 + 8][K2 + 4 + (lane & 3)];
            }
#pragma unroll
            for (int tn = 0; tn < TN; tn++) {
                int bn = warp_n * WN + tn * 8 + (lane >> 2);
                uint32_t b0 = Wt[bn][K2 + (lane & 3)];
                uint32_t b1 = Wt[bn][K2 + 4 + (lane & 3)];
                mma_f16(c[0][tn], a[0], b0, b1);
                mma_f16(c[1][tn], a[1], b0, b1);
            }
        }
        __syncthreads();
    }

#pragma unroll
    for (int tm = 0; tm < 2; tm++) {
        int rbase = row0 + warp_m * 32 + tm * 16 + (lane >> 2);
#pragma unroll
        for (int half = 0; half < 2; half++) {
            int rr = rbase + half * 8;
            if (rr < NN) {
                float sc = SCALE ? __ldg(g_dinv + rr) : 1.f;
#pragma unroll
                for (int tn = 0; tn < TN; tn++) {
                    int n = warp_n * WN + tn * 8 + 2 * (lane & 3);
                    *(half2*)(C + (size_t)rr * BN + n) =
                        __floats2half2_rn(c[tm][tn][2 * half] * sc,
                                          c[tm][tn][2 * half + 1] * sc);
                }
            }
        }
    }
}

__global__ void __launch_bounds__(256) k_gemm1(const float* __restrict__ A,
                                               const float* __restrict__ W) {
    gemm_f16_body<128, false, false>(A, W, g_h1);
}
__global__ void __launch_bounds__(256) k_gemm2(const float* __restrict__ W) {
    gemm_f16_body<64, true, true>(g_agg, W, g_h2);
}

// ---------------- layer-1 aggregation: warp per node, fp16 gather, fused relu+dropout ----------------
__device__ __forceinline__ void acc_h4(float4& ae, uint2 u, float w) {
    float2 f0 = __half22float2(*reinterpret_cast<half2*>(&u.x));
    float2 f1 = __half22float2(*reinterpret_cast<half2*>(&u.y));
    ae.x = fmaf(f0.x, w, ae.x); ae.y = fmaf(f0.y, w, ae.y);
    ae.z = fmaf(f1.x, w, ae.z); ae.w = fmaf(f1.y, w, ae.w);
}

__global__ void __launch_bounds__(256) k_agg1(const float* __restrict__ b1) {
    int d = (blockIdx.x * 256 + threadIdx.x) >> 5;
    if (d >= NN) return;
    int lane = threadIdx.x & 31;
    float dind = __ldg(g_dinv + d);

    const uint2* hb = (const uint2*)g_h1;
    float4 ae = make_float4(0.f, 0.f, 0.f, 0.f);
    acc_h4(ae, __ldg(hb + (size_t)d * 32 + lane), dind);   // self term

    int beg = __ldg(g_off + d), end = __ldg(g_off + d + 1);
    int i = beg;
    for (; i + 4 <= end; i += 4) {
        int2 e0 = __ldg(g_edge + i + 0);
        int2 e1 = __ldg(g_edge + i + 1);
        int2 e2 = __ldg(g_edge + i + 2);
        int2 e3 = __ldg(g_edge + i + 3);
        uint2 u0 = __ldg(hb + (size_t)e0.x * 32 + lane);
        uint2 u1 = __ldg(hb + (size_t)e1.x * 32 + lane);
        uint2 u2 = __ldg(hb + (size_t)e2.x * 32 + lane);
        uint2 u3 = __ldg(hb + (size_t)e3.x * 32 + lane);
        acc_h4(ae, u0, __int_as_float(e0.y));
        acc_h4(ae, u1, __int_as_float(e1.y));
        acc_h4(ae, u2, __int_as_float(e2.y));
        acc_h4(ae, u3, __int_as_float(e3.y));
    }
    for (; i < end; i++) {
        int2 e = __ldg(g_edge + i);
        acc_h4(ae, __ldg(hb + (size_t)e.x * 32 + lane), __int_as_float(e.y));
    }

    int f = lane * 4;
    float4 bv = __ldg((const float4*)(b1 + f));
    unsigned base = (unsigned)d * 128u + (unsigned)f;
    float m0 = drop_mul(base + 0), m1 = drop_mul(base + 1);
    float m2 = drop_mul(base + 2), m3 = drop_mul(base + 3);
    float4 acc;
    acc.x = fmaxf(fmaf(ae.x, dind, bv.x), 0.f) * m0;
    acc.y = fmaxf(fmaf(ae.y, dind, bv.y), 0.f) * m1;
    acc.z = fmaxf(fmaf(ae.z, dind, bv.z), 0.f) * m2;
    acc.w = fmaxf(fmaf(ae.w, dind, bv.w), 0.f) * m3;

    half2 h0 = __floats2half2_rn(acc.x, acc.y);
    half2 h1 = __floats2half2_rn(acc.z, acc.w);
    uint2 st = make_uint2(*(uint32_t*)&h0, *(uint32_t*)&h1);
    *(uint2*)(g_agg + (size_t)d * 128 + f) = st;
}

// ---------------- layer-2 aggregation: half warp per node, fp16 gather (pre-scaled) ----------------
__global__ void __launch_bounds__(256) k_agg2(const float* __restrict__ b2,
                                              float* __restrict__ out) {
    int t = blockIdx.x * 256 + threadIdx.x;
    int d = t >> 4;
    if (d >= NN) return;
    int l = t & 15;
    float dind = __ldg(g_dinv + d);

    const uint2* hb = (const uint2*)g_h2;
    float4 ae = make_float4(0.f, 0.f, 0.f, 0.f);
    acc_h4(ae, __ldg(hb + (size_t)d * 16 + l), 1.f);   // self term (pre-scaled)

    int beg = __ldg(g_off + d), end = __ldg(g_off + d + 1);
    int i = beg;
    for (; i + 4 <= end; i += 4) {
        int2 e0 = __ldg(g_edge + i + 0);
        int2 e1 = __ldg(g_edge + i + 1);
        int2 e2 = __ldg(g_edge + i + 2);
        int2 e3 = __ldg(g_edge + i + 3);
        uint2 u0 = __ldg(hb + (size_t)e0.x * 16 + l);
        uint2 u1 = __ldg(hb + (size_t)e1.x * 16 + l);
        uint2 u2 = __ldg(hb + (size_t)e2.x * 16 + l);
        uint2 u3 = __ldg(hb + (size_t)e3.x * 16 + l);
        acc_h4(ae, u0, 1.f); acc_h4(ae, u1, 1.f);
        acc_h4(ae, u2, 1.f); acc_h4(ae, u3, 1.f);
    }
    for (; i < end; i++) {
        int2 e = __ldg(g_edge + i);
        acc_h4(ae, __ldg(hb + (size_t)e.x * 16 + l), 1.f);
    }

    float4 bv = __ldg((const float4*)(b2 + l * 4));
    float4 acc;
    acc.x = fmaf(ae.x, dind, bv.x);
    acc.y = fmaf(ae.y, dind, bv.y);
    acc.z = fmaf(ae.z, dind, bv.z);
    acc.w = fmaf(ae.w, dind, bv.w);
    *(float4*)(out + (size_t)d * 64 + l * 4) = acc;
}

// ---------------- launch: gemm1 forked; cleanup forked + JOINED at the end ----------------
extern "C" void kernel_launch(void* const* d_in, const int* in_sizes, int n_in,
                              void* d_out, int out_size) {
    const float* x  = (const float*)d_in[0];
    const int*   ei = (const int*)d_in[1];
    const float* W1 = (const float*)d_in[2];
    const float* b1 = (const float*)d_in[3];
    const float* W2 = (const float*)d_in[4];
    const float* b2 = (const float*)d_in[5];
    const int* src = ei;
    const int* dst = ei + NE;
    float* out = (float*)d_out;

    static cudaStream_t sB = nullptr, sC = nullptr;
    static cudaEvent_t evRoot = nullptr, evB = nullptr, evScan = nullptr, evC = nullptr;
    if (sB == nullptr) {
        cudaStreamCreateWithFlags(&sB, cudaStreamNonBlocking);
        cudaStreamCreateWithFlags(&sC, cudaStreamNonBlocking);
        cudaEventCreateWithFlags(&evRoot, cudaEventDisableTiming);
        cudaEventCreateWithFlags(&evB, cudaEventDisableTiming);
        cudaEventCreateWithFlags(&evScan, cudaEventDisableTiming);
        cudaEventCreateWithFlags(&evC, cudaEventDisableTiming);
    }

    cudaEventRecord(evRoot, 0);
    cudaStreamWaitEvent(sB, evRoot, 0);

    // stream B: GEMM1 (fp16 tensor cores) — hidden under CSR build
    k_gemm1<<<(NN + 127) / 128, 256, 0, sB>>>(x, W1);
    cudaEventRecord(evB, sB);

    // default stream: CSR build (zero-invariant: g_dege/g_stat are zero at entry;
    // static init covers the first call, k_cleanup below restores it for replays)
    k_deg_count<<<(NE / 4 + 511) / 512, 512>>>(dst);
    k_csr_scan<<<NBLK, 256>>>();
    cudaEventRecord(evScan, 0);
    k_fill<<<(NE / 4 + 511) / 512, 512>>>(src, dst);

    // stream C: restore zero-invariant off the critical path (runs under agg1)
    cudaStreamWaitEvent(sC, evScan, 0);
    k_cleanup<<<98, 256, 0, sC>>>();
    cudaEventRecord(evC, sC);

    cudaStreamWaitEvent(0, evB, 0);

    k_agg1<<<(NN * 32 + 255) / 256, 256>>>(b1);       // + relu + dropout (threefry fused)
    k_gemm2<<<(NN + 127) / 128, 256>>>(W2);
    k_agg2<<<(NN * 16 + 255) / 256, 256>>>(b2, out);

    // join stream C back into the origin stream (required for graph capture;
    // cleanup finished long ago, so this wait is free)
    cudaStreamWaitEvent(0, evC, 0);
}